// round 5
// baseline (speedup 1.0000x reference)
#include <cuda_runtime.h>

#define W 512
#define H 512
#define B 16
#define HW (H*W)

// Scratch: grayscale image (device global, no allocation)
__device__ float g_gray[B * HW];

// ---------------------------------------------------------------------------
// Kernel 1: gray = 0.114*c0 + 0.587*c1 + 0.299*c2 (BGR->gray), plus channel
// shuffle x5[b,c] = x[b, perm[b,c]]. float4 vectorized.
// ---------------------------------------------------------------------------
__global__ __launch_bounds__(256) void k1_gray_shuffle(
    const float* __restrict__ x, const int* __restrict__ perm,
    float* __restrict__ x5)
{
    const int nv = HW / 4;
    int t = blockIdx.x * 256 + threadIdx.x;
    if (t >= B * nv) return;
    int b = t / nv;
    int p = t - b * nv;

    const float4* xb = (const float4*)(x + (size_t)b * 3 * HW);
    float4 c0 = xb[p];
    float4 c1 = xb[nv + p];
    float4 c2 = xb[2 * nv + p];

    float4 gr;
    gr.x = 0.114f * c0.x + 0.587f * c1.x + 0.299f * c2.x;
    gr.y = 0.114f * c0.y + 0.587f * c1.y + 0.299f * c2.y;
    gr.z = 0.114f * c0.z + 0.587f * c1.z + 0.299f * c2.z;
    gr.w = 0.114f * c0.w + 0.587f * c1.w + 0.299f * c2.w;
    ((float4*)g_gray)[b * nv + p] = gr;

    int p0 = perm[b * 3 + 0];
    int p1 = perm[b * 3 + 1];
    int p2 = perm[b * 3 + 2];
    float4* o = (float4*)(x5 + (size_t)b * 3 * HW);
    o[p]          = (p0 == 0) ? c0 : ((p0 == 1) ? c1 : c2);
    o[nv + p]     = (p1 == 0) ? c0 : ((p1 == 1) ? c1 : c2);
    o[2 * nv + p] = (p2 == 0) ? c0 : ((p2 == 1) ? c1 : c2);
}

// ---------------------------------------------------------------------------
// Kernel 2: fused gaussian blur (reflect pad) -> sobel (replicate pad) ->
// magnitude -> NMS (zero pad). One 32x32 output tile per block.
// ---------------------------------------------------------------------------
__device__ __forceinline__ int refl(int i, int n) {
    if (i < 0) i = -i;
    if (i >= n) i = 2 * n - 2 - i;
    return i;
}

__global__ __launch_bounds__(256) void k2_canny(float* __restrict__ outmag)
{
    // gray tile: rel rows/cols [-4..35] (40x40)
    __shared__ float sg[40 * 40];
    // horizontal-blurred: rows [-4..35] x cols [-2..33] (40x36)
    __shared__ float st[40 * 36];
    // blurred: rows/cols [-2..33] (36x36)
    __shared__ float sb[36 * 36];
    // magnitude: rows/cols [-1..32] (34x34), 0 outside image
    __shared__ float sm[34 * 34];

    const int tid = threadIdx.x;
    const int b = blockIdx.z;
    const int ty0 = blockIdx.y * 32;
    const int tx0 = blockIdx.x * 32;
    const float* g = g_gray + (size_t)b * HW;

    for (int i = tid; i < 1600; i += 256) {
        int r = i / 40, c = i - 40 * r;
        sg[i] = g[refl(ty0 + r - 4, H) * W + refl(tx0 + c - 4, W)];
    }
    __syncthreads();

    // Gaussian 5-tap (sigma=1): exp(-k^2/2)/sum
    const float w0 = 0.05448868f, w1 = 0.24420136f, w2 = 0.40261996f;

    for (int i = tid; i < 40 * 36; i += 256) {
        int r = i / 36, c = i - 36 * r;
        const float* p = &sg[r * 40 + c];
        st[i] = w0 * (p[0] + p[4]) + w1 * (p[1] + p[3]) + w2 * p[2];
    }
    __syncthreads();

    for (int i = tid; i < 36 * 36; i += 256) {
        int r = i / 36, c = i - 36 * r;
        const float* p = &st[r * 36 + c];
        sb[i] = w0 * (p[0] + p[4 * 36]) + w1 * (p[36] + p[3 * 36]) + w2 * p[2 * 36];
    }
    __syncthreads();

    // magnitude on rel [-1..32]^2; sobel neighbor rows/cols clamp to image
    for (int i = tid; i < 34 * 34; i += 256) {
        int r = i / 34, c = i - 34 * r;
        int gy = ty0 + r - 1, gx = tx0 + c - 1;
        float v = 0.f;
        if (gy >= 0 && gy < H && gx >= 0 && gx < W) {
            int ym = max(gy - 1, 0) - ty0 + 2;
            int yc = gy - ty0 + 2;
            int yp = min(gy + 1, H - 1) - ty0 + 2;
            int xm = max(gx - 1, 0) - tx0 + 2;
            int xc = gx - tx0 + 2;
            int xp = min(gx + 1, W - 1) - tx0 + 2;
            float b00 = sb[ym * 36 + xm], b01 = sb[ym * 36 + xc], b02 = sb[ym * 36 + xp];
            float b10 = sb[yc * 36 + xm],                          b12 = sb[yc * 36 + xp];
            float b20 = sb[yp * 36 + xm], b21 = sb[yp * 36 + xc], b22 = sb[yp * 36 + xp];
            float gxv = (b02 - b00) + 2.f * (b12 - b10) + (b22 - b20);
            float gyv = (b20 - b00) + 2.f * (b21 - b01) + (b22 - b02);
            v = sqrtf(gxv * gxv + gyv * gyv + 1e-6f);
        }
        sm[i] = v;
    }
    __syncthreads();

    // output: NMS
    for (int i = tid; i < 1024; i += 256) {
        int y = i >> 5, x = i & 31;
        int gy = ty0 + y, gx = tx0 + x;
        int ym = max(gy - 1, 0) - ty0 + 2;
        int yc = gy - ty0 + 2;
        int yp = min(gy + 1, H - 1) - ty0 + 2;
        int xm = max(gx - 1, 0) - tx0 + 2;
        int xc = gx - tx0 + 2;
        int xp = min(gx + 1, W - 1) - tx0 + 2;
        float b00 = sb[ym * 36 + xm], b01 = sb[ym * 36 + xc], b02 = sb[ym * 36 + xp];
        float b10 = sb[yc * 36 + xm],                          b12 = sb[yc * 36 + xp];
        float b20 = sb[yp * 36 + xm], b21 = sb[yp * 36 + xc], b22 = sb[yp * 36 + xp];
        float gxv = (b02 - b00) + 2.f * (b12 - b10) + (b22 - b20);
        float gyv = (b20 - b00) + 2.f * (b21 - b01) + (b22 - b02);

        float deg = atan2f(gyv, gxv) * 57.295779513082323f;
        int q = (int)rintf(deg / 45.0f);      // [-4..4], half-to-even like jnp.round
        int idx = q & 7;                      // mod 8

        // offsets (dy,dx) packed 2 bits each (value+1): OFFS table order
        int dy = ((0x1A9  >> (2 * idx)) & 3) - 1;
        int dx = ((0x901A >> (2 * idx)) & 3) - 1;

        float m   = sm[(y + 1) * 34 + (x + 1)];
        float pos = m - sm[(y + 1 + dy) * 34 + (x + 1 + dx)];
        float neg = m - sm[(y + 1 - dy) * 34 + (x + 1 - dx)];
        outmag[(size_t)b * HW + gy * W + gx] = (fminf(pos, neg) > 0.f) ? m : 0.f;
    }
}

// ---------------------------------------------------------------------------
// Kernel 3: 4 dilations (max-pool SAME, k=3,5,7,9) in one pass via
// separable incremental maxes. suppressed mag >= 0 so zero-padding == -inf.
// ---------------------------------------------------------------------------
__global__ __launch_bounds__(256) void k3_dilate(
    const float* __restrict__ mag,
    float* __restrict__ o3, float* __restrict__ o5,
    float* __restrict__ o7, float* __restrict__ o9)
{
    __shared__ float s[40 * 40];          // mag, halo 4
    __shared__ float v3[32 * 40];
    __shared__ float v5[32 * 40];
    __shared__ float v7[32 * 40];
    __shared__ float v9[32 * 40];

    const int tid = threadIdx.x;
    const int b = blockIdx.z;
    const int ty0 = blockIdx.y * 32;
    const int tx0 = blockIdx.x * 32;
    const float* m = mag + (size_t)b * HW;

    for (int i = tid; i < 1600; i += 256) {
        int r = i / 40, c = i - 40 * r;
        int gy = ty0 + r - 4, gx = tx0 + c - 4;
        s[i] = (gy >= 0 && gy < H && gx >= 0 && gx < W) ? m[gy * W + gx] : 0.f;
    }
    __syncthreads();

    // vertical incremental maxes for output rows (0..31), all 40 cols
    for (int i = tid; i < 1280; i += 256) {
        int r = i / 40, c = i - 40 * r;
        const float* p = &s[r * 40 + c];
        float t3 = fmaxf(fmaxf(p[3 * 40], p[4 * 40]), p[5 * 40]);
        float t5 = fmaxf(t3, fmaxf(p[2 * 40], p[6 * 40]));
        float t7 = fmaxf(t5, fmaxf(p[1 * 40], p[7 * 40]));
        float t9 = fmaxf(t7, fmaxf(p[0],      p[8 * 40]));
        v3[i] = t3; v5[i] = t5; v7[i] = t7; v9[i] = t9;
    }
    __syncthreads();

    for (int i = tid; i < 1024; i += 256) {
        int y = i >> 5, x = i & 31;
        int base = y * 40 + x;   // col index x+4 is the center; window offsets below

        float a3 = fmaxf(fmaxf(v3[base + 3], v3[base + 4]), v3[base + 5]);

        float a5 = fmaxf(fmaxf(v5[base + 2], v5[base + 3]),
                   fmaxf(v5[base + 4], fmaxf(v5[base + 5], v5[base + 6])));

        float a7 = fmaxf(fmaxf(fmaxf(v7[base + 1], v7[base + 2]),
                               fmaxf(v7[base + 3], v7[base + 4])),
                         fmaxf(fmaxf(v7[base + 5], v7[base + 6]), v7[base + 7]));

        float a9 = fmaxf(fmaxf(fmaxf(fmaxf(v9[base + 0], v9[base + 1]),
                                     fmaxf(v9[base + 2], v9[base + 3])),
                               fmaxf(fmaxf(v9[base + 4], v9[base + 5]),
                                     fmaxf(v9[base + 6], v9[base + 7]))),
                         v9[base + 8]);

        size_t o = (size_t)b * HW + (size_t)(ty0 + y) * W + (tx0 + x);
        o3[o] = a3; o5[o] = a5; o7[o] = a7; o9[o] = a9;
    }
}

// ---------------------------------------------------------------------------
extern "C" void kernel_launch(void* const* d_in, const int* in_sizes, int n_in,
                              void* d_out, int out_size)
{
    const float* x    = (const float*)d_in[0];
    const int*   perm = (const int*)d_in[1];
    float* out = (float*)d_out;

    float* o_mag = out;
    float* o_d3  = out + 1 * (size_t)B * HW;
    float* o_d5  = out + 2 * (size_t)B * HW;
    float* o_d7  = out + 3 * (size_t)B * HW;
    float* o_d9  = out + 4 * (size_t)B * HW;
    float* o_x5  = out + 5 * (size_t)B * HW;

    int nthreads1 = (B * HW / 4);
    k1_gray_shuffle<<<(nthreads1 + 255) / 256, 256>>>(x, perm, o_x5);

    dim3 g2(W / 32, H / 32, B);
    k2_canny<<<g2, 256>>>(o_mag);
    k3_dilate<<<g2, 256>>>(o_mag, o_d3, o_d5, o_d7, o_d9);
}

// round 9
// speedup vs baseline: 1.0125x; 1.0125x over previous
#include <cuda_runtime.h>

#define W 512
#define H 512
#define B 16
#define HW (H*W)

// Scratch: grayscale image (device global, no allocation)
__device__ float g_gray[B * HW];

// ---------------------------------------------------------------------------
// Kernel 1: gray = 0.114*c0 + 0.587*c1 + 0.299*c2 (BGR->gray), plus channel
// shuffle x5[b,c] = x[b, perm[b,c]]. float4 vectorized.
// ---------------------------------------------------------------------------
__global__ __launch_bounds__(256) void k1_gray_shuffle(
    const float* __restrict__ x, const int* __restrict__ perm,
    float* __restrict__ x5)
{
    const int nv = HW / 4;
    int t = blockIdx.x * 256 + threadIdx.x;
    if (t >= B * nv) return;
    int b = t / nv;
    int p = t - b * nv;

    const float4* xb = (const float4*)(x + (size_t)b * 3 * HW);
    float4 c0 = xb[p];
    float4 c1 = xb[nv + p];
    float4 c2 = xb[2 * nv + p];

    float4 gr;
    gr.x = 0.114f * c0.x + 0.587f * c1.x + 0.299f * c2.x;
    gr.y = 0.114f * c0.y + 0.587f * c1.y + 0.299f * c2.y;
    gr.z = 0.114f * c0.z + 0.587f * c1.z + 0.299f * c2.z;
    gr.w = 0.114f * c0.w + 0.587f * c1.w + 0.299f * c2.w;
    ((float4*)g_gray)[b * nv + p] = gr;

    int p0 = perm[b * 3 + 0];
    int p1 = perm[b * 3 + 1];
    int p2 = perm[b * 3 + 2];
    float4* o = (float4*)(x5 + (size_t)b * 3 * HW);
    o[p]          = (p0 == 0) ? c0 : ((p0 == 1) ? c1 : c2);
    o[nv + p]     = (p1 == 0) ? c0 : ((p1 == 1) ? c1 : c2);
    o[2 * nv + p] = (p2 == 0) ? c0 : ((p2 == 1) ? c1 : c2);
}

// ---------------------------------------------------------------------------
// Kernel 2: fused gaussian blur (reflect pad) -> sobel (replicate pad) ->
// magnitude -> NMS (zero pad). One 32x32 output tile per block, 512 threads.
// Direction axis computed by comparisons (no atan2f) during the magnitude
// stage; NMS stage is a pure table lookup + 3 smem reads.
// ---------------------------------------------------------------------------
__device__ __forceinline__ int refl(int i, int n) {
    if (i < 0) i = -i;
    if (i >= n) i = 2 * n - 2 - i;
    return i;
}

__global__ __launch_bounds__(512) void k2_canny(float* __restrict__ outmag)
{
    __shared__ float sg[40 * 40];            // gray, rel [-4..35]^2
    __shared__ float st[40 * 36];            // h-blur, rows [-4..35] cols [-2..33]
    __shared__ float sb[36 * 36];            // blur, rel [-2..33]^2
    __shared__ float sm[34 * 34];            // magnitude, rel [-1..32]^2 (0 outside)
    __shared__ unsigned char sax[32 * 32];   // NMS axis per output pixel

    const int tid = threadIdx.x;
    const int b = blockIdx.z;
    const int ty0 = blockIdx.y * 32;
    const int tx0 = blockIdx.x * 32;
    const float* g = g_gray + (size_t)b * HW;

    for (int i = tid; i < 1600; i += 512) {
        int r = i / 40, c = i - 40 * r;
        sg[i] = g[refl(ty0 + r - 4, H) * W + refl(tx0 + c - 4, W)];
    }
    __syncthreads();

    // Gaussian 5-tap (sigma=1): exp(-k^2/2)/sum
    const float w0 = 0.05448868f, w1 = 0.24420136f, w2 = 0.40261996f;

    for (int i = tid; i < 40 * 36; i += 512) {
        int r = i / 36, c = i - 36 * r;
        const float* p = &sg[r * 40 + c];
        st[i] = w0 * (p[0] + p[4]) + w1 * (p[1] + p[3]) + w2 * p[2];
    }
    __syncthreads();

    for (int i = tid; i < 36 * 36; i += 512) {
        int r = i / 36, c = i - 36 * r;
        const float* p = &st[r * 36 + c];
        sb[i] = w0 * (p[0] + p[4 * 36]) + w1 * (p[36] + p[3 * 36]) + w2 * p[2 * 36];
    }
    __syncthreads();

    // magnitude on rel [-1..32]^2; sobel neighbor rows/cols clamp to image.
    // Interior 32x32 additionally gets its NMS axis (direction mod 4).
    for (int i = tid; i < 34 * 34; i += 512) {
        int r = i / 34, c = i - 34 * r;
        int gy = ty0 + r - 1, gx = tx0 + c - 1;
        float v = 0.f;
        if (gy >= 0 && gy < H && gx >= 0 && gx < W) {
            int ym = max(gy - 1, 0) - ty0 + 2;
            int yc = gy - ty0 + 2;
            int yp = min(gy + 1, H - 1) - ty0 + 2;
            int xm = max(gx - 1, 0) - tx0 + 2;
            int xc = gx - tx0 + 2;
            int xp = min(gx + 1, W - 1) - tx0 + 2;
            float b00 = sb[ym * 36 + xm], b01 = sb[ym * 36 + xc], b02 = sb[ym * 36 + xp];
            float b10 = sb[yc * 36 + xm],                          b12 = sb[yc * 36 + xp];
            float b20 = sb[yp * 36 + xm], b21 = sb[yp * 36 + xc], b22 = sb[yp * 36 + xp];
            float gxv = (b02 - b00) + 2.f * (b12 - b10) + (b22 - b20);
            float gyv = (b20 - b00) + 2.f * (b21 - b01) + (b22 - b02);
            v = sqrtf(gxv * gxv + gyv * gyv + 1e-6f);

            if ((unsigned)(r - 1) < 32u && (unsigned)(c - 1) < 32u) {
                // axis = round(atan2(gy,gx)/45deg) mod 4, via sector comparisons
                float ax = fabsf(gxv), ay = fabsf(gyv);
                int axis;
                if (ay < 0.41421356f * ax)      axis = 0;   // tan(22.5)
                else if (ay > 2.41421356f * ax) axis = 2;   // tan(67.5)
                else axis = (gxv * gyv >= 0.f) ? 1 : 3;
                sax[(r - 1) * 32 + (c - 1)] = (unsigned char)axis;
            }
        }
        sm[i] = v;
    }
    __syncthreads();

    // output: NMS — min(center-nbr, center-opposite_nbr) > 0 keeps center
    for (int i = tid; i < 1024; i += 512) {
        int y = i >> 5, x = i & 31;
        int axis = sax[i];
        int dy = (axis == 0) ? 0 : 1;                       // (0,1)(1,1)(1,0)(1,-1)
        int dx = (axis == 2) ? 0 : ((axis == 3) ? -1 : 1);

        float m   = sm[(y + 1) * 34 + (x + 1)];
        float pos = m - sm[(y + 1 + dy) * 34 + (x + 1 + dx)];
        float neg = m - sm[(y + 1 - dy) * 34 + (x + 1 - dx)];
        outmag[(size_t)b * HW + (ty0 + y) * W + (tx0 + x)] =
            (fminf(pos, neg) > 0.f) ? m : 0.f;
    }
}

// ---------------------------------------------------------------------------
// Kernel 3: 4 dilations (max-pool SAME, k=3,5,7,9) in one pass via
// separable incremental maxes. suppressed mag >= 0 so zero-padding == -inf.
// ---------------------------------------------------------------------------
__global__ __launch_bounds__(512) void k3_dilate(
    const float* __restrict__ mag,
    float* __restrict__ o3, float* __restrict__ o5,
    float* __restrict__ o7, float* __restrict__ o9)
{
    __shared__ float s[40 * 40];          // mag, halo 4
    __shared__ float v3[32 * 40];
    __shared__ float v5[32 * 40];
    __shared__ float v7[32 * 40];
    __shared__ float v9[32 * 40];

    const int tid = threadIdx.x;
    const int b = blockIdx.z;
    const int ty0 = blockIdx.y * 32;
    const int tx0 = blockIdx.x * 32;
    const float* m = mag + (size_t)b * HW;

    for (int i = tid; i < 1600; i += 512) {
        int r = i / 40, c = i - 40 * r;
        int gy = ty0 + r - 4, gx = tx0 + c - 4;
        s[i] = (gy >= 0 && gy < H && gx >= 0 && gx < W) ? m[gy * W + gx] : 0.f;
    }
    __syncthreads();

    // vertical incremental maxes for output rows (0..31), all 40 cols
    for (int i = tid; i < 1280; i += 512) {
        int r = i / 40, c = i - 40 * r;
        const float* p = &s[r * 40 + c];
        float t3 = fmaxf(fmaxf(p[3 * 40], p[4 * 40]), p[5 * 40]);
        float t5 = fmaxf(t3, fmaxf(p[2 * 40], p[6 * 40]));
        float t7 = fmaxf(t5, fmaxf(p[1 * 40], p[7 * 40]));
        float t9 = fmaxf(t7, fmaxf(p[0],      p[8 * 40]));
        v3[i] = t3; v5[i] = t5; v7[i] = t7; v9[i] = t9;
    }
    __syncthreads();

    for (int i = tid; i < 1024; i += 512) {
        int y = i >> 5, x = i & 31;
        int base = y * 40 + x;   // center col is x+4; window offsets below

        float a3 = fmaxf(fmaxf(v3[base + 3], v3[base + 4]), v3[base + 5]);

        float a5 = fmaxf(fmaxf(v5[base + 2], v5[base + 3]),
                   fmaxf(v5[base + 4], fmaxf(v5[base + 5], v5[base + 6])));

        float a7 = fmaxf(fmaxf(fmaxf(v7[base + 1], v7[base + 2]),
                               fmaxf(v7[base + 3], v7[base + 4])),
                         fmaxf(fmaxf(v7[base + 5], v7[base + 6]), v7[base + 7]));

        float a9 = fmaxf(fmaxf(fmaxf(fmaxf(v9[base + 0], v9[base + 1]),
                                     fmaxf(v9[base + 2], v9[base + 3])),
                               fmaxf(fmaxf(v9[base + 4], v9[base + 5]),
                                     fmaxf(v9[base + 6], v9[base + 7]))),
                         v9[base + 8]);

        size_t o = (size_t)b * HW + (size_t)(ty0 + y) * W + (tx0 + x);
        o3[o] = a3; o5[o] = a5; o7[o] = a7; o9[o] = a9;
    }
}

// ---------------------------------------------------------------------------
extern "C" void kernel_launch(void* const* d_in, const int* in_sizes, int n_in,
                              void* d_out, int out_size)
{
    const float* x    = (const float*)d_in[0];
    const int*   perm = (const int*)d_in[1];
    float* out = (float*)d_out;

    float* o_mag = out;
    float* o_d3  = out + 1 * (size_t)B * HW;
    float* o_d5  = out + 2 * (size_t)B * HW;
    float* o_d7  = out + 3 * (size_t)B * HW;
    float* o_d9  = out + 4 * (size_t)B * HW;
    float* o_x5  = out + 5 * (size_t)B * HW;

    int nthreads1 = (B * HW / 4);
    k1_gray_shuffle<<<(nthreads1 + 255) / 256, 256>>>(x, perm, o_x5);

    dim3 g2(W / 32, H / 32, B);
    k2_canny<<<g2, 512>>>(o_mag);
    k3_dilate<<<g2, 512>>>(o_mag, o_d3, o_d5, o_d7, o_d9);
}

// round 11
// speedup vs baseline: 1.1569x; 1.1426x over previous
#include <cuda_runtime.h>

#define W 512
#define H 512
#define B 16
#define HW (H*W)

#define TX 64
#define TY 32

// Scratch: grayscale image (device global, no allocation)
__device__ float g_gray[B * HW];

// ---------------------------------------------------------------------------
// Kernel 1: gray + channel shuffle. Each thread: 2 float4 chunks (MLP=6).
// ---------------------------------------------------------------------------
__global__ __launch_bounds__(256) void k1_gray_shuffle(
    const float* __restrict__ x, const int* __restrict__ perm,
    float* __restrict__ x5)
{
    const int nv = HW / 4;          // float4 per channel-plane
    const int half = nv / 2;
    int t = blockIdx.x * 256 + threadIdx.x;
    if (t >= B * half) return;
    int b = t / half;
    int p = t - b * half;

    const float4* xb = (const float4*)(x + (size_t)b * 3 * HW);
    float4 c0a = xb[p],          c0b = xb[p + half];
    float4 c1a = xb[nv + p],     c1b = xb[nv + p + half];
    float4 c2a = xb[2*nv + p],   c2b = xb[2*nv + p + half];

    float4 ga, gb;
    ga.x = 0.114f*c0a.x + 0.587f*c1a.x + 0.299f*c2a.x;
    ga.y = 0.114f*c0a.y + 0.587f*c1a.y + 0.299f*c2a.y;
    ga.z = 0.114f*c0a.z + 0.587f*c1a.z + 0.299f*c2a.z;
    ga.w = 0.114f*c0a.w + 0.587f*c1a.w + 0.299f*c2a.w;
    gb.x = 0.114f*c0b.x + 0.587f*c1b.x + 0.299f*c2b.x;
    gb.y = 0.114f*c0b.y + 0.587f*c1b.y + 0.299f*c2b.y;
    gb.z = 0.114f*c0b.z + 0.587f*c1b.z + 0.299f*c2b.z;
    gb.w = 0.114f*c0b.w + 0.587f*c1b.w + 0.299f*c2b.w;
    ((float4*)g_gray)[b * nv + p]        = ga;
    ((float4*)g_gray)[b * nv + p + half] = gb;

    int p0 = perm[b * 3 + 0];
    int p1 = perm[b * 3 + 1];
    int p2 = perm[b * 3 + 2];
    float4* o = (float4*)(x5 + (size_t)b * 3 * HW);
    o[p]               = (p0 == 0) ? c0a : ((p0 == 1) ? c1a : c2a);
    o[p + half]        = (p0 == 0) ? c0b : ((p0 == 1) ? c1b : c2b);
    o[nv + p]          = (p1 == 0) ? c0a : ((p1 == 1) ? c1a : c2a);
    o[nv + p + half]   = (p1 == 0) ? c0b : ((p1 == 1) ? c1b : c2b);
    o[2*nv + p]        = (p2 == 0) ? c0a : ((p2 == 1) ? c1a : c2a);
    o[2*nv + p + half] = (p2 == 0) ? c0b : ((p2 == 1) ? c1b : c2b);
}

// ---------------------------------------------------------------------------
// Kernel 2: fused gaussian(reflect) -> sobel(replicate) -> magnitude ->
// NMS(zero pad). 64x32 tile per block, 512 threads, float4 loads/stores.
// ---------------------------------------------------------------------------
__device__ __forceinline__ int refl(int i, int n) {
    if (i < 0) i = -i;
    if (i >= n) i = 2 * n - 2 - i;
    return i;
}

__global__ __launch_bounds__(512) void k2_canny(float* __restrict__ outmag)
{
    __shared__ float sg[40 * 72];            // gray: rows -4..35, cols -4..67
    __shared__ float st[40 * 68];            // h-blur: rows -4..35, cols -2..65
    __shared__ float sb[36 * 68];            // blur: rows -2..33, cols -2..65
    __shared__ float sm[34 * 66];            // mag: rows -1..32, cols -1..64
    __shared__ unsigned char sax[32 * 64];   // NMS axis per output pixel

    const int tid = threadIdx.x;
    const int b = blockIdx.z;
    const int ty0 = blockIdx.y * TY;
    const int tx0 = blockIdx.x * TX;
    const float* g = g_gray + (size_t)b * HW;
    const bool xborder = (blockIdx.x == 0) | (blockIdx.x == (W/TX - 1));

    if (!xborder) {
        // interior: float4 row loads, cols tx0-4 .. tx0+67 (16B aligned)
        for (int i = tid; i < 40 * 18; i += 512) {
            int r = i / 18, c4 = i - 18 * r;
            int gyr = refl(ty0 + r - 4, H);
            const float4* row = (const float4*)(g + gyr * W + tx0 - 4);
            *(float4*)&sg[r * 72 + c4 * 4] = row[c4];
        }
    } else {
        for (int i = tid; i < 40 * 72; i += 512) {
            int r = i / 72, c = i - 72 * r;
            sg[i] = g[refl(ty0 + r - 4, H) * W + refl(tx0 + c - 4, W)];
        }
    }
    __syncthreads();

    // Gaussian 5-tap (sigma=1)
    const float w0 = 0.05448868f, w1 = 0.24420136f, w2 = 0.40261996f;

    for (int i = tid; i < 40 * 68; i += 512) {
        int r = i / 68, c = i - 68 * r;
        const float* p = &sg[r * 72 + c];
        st[i] = w0 * (p[0] + p[4]) + w1 * (p[1] + p[3]) + w2 * p[2];
    }
    __syncthreads();

    for (int i = tid; i < 36 * 68; i += 512) {
        int r = i / 68, c = i - 68 * r;
        const float* p = &st[r * 68 + c];
        sb[i] = w0 * (p[0] + p[4 * 68]) + w1 * (p[68] + p[3 * 68]) + w2 * p[2 * 68];
    }
    __syncthreads();

    // magnitude rows -1..32, cols -1..64; sobel neighbors clamp to image
    for (int i = tid; i < 34 * 66; i += 512) {
        int r = i / 66, c = i - 66 * r;
        int gy = ty0 + r - 1, gx = tx0 + c - 1;
        float v = 0.f;
        if (gy >= 0 && gy < H && gx >= 0 && gx < W) {
            int ym = max(gy - 1, 0) - ty0 + 2;
            int yc = gy - ty0 + 2;
            int yp = min(gy + 1, H - 1) - ty0 + 2;
            int xm = max(gx - 1, 0) - tx0 + 2;
            int xc = gx - tx0 + 2;
            int xp = min(gx + 1, W - 1) - tx0 + 2;
            float b00 = sb[ym * 68 + xm], b01 = sb[ym * 68 + xc], b02 = sb[ym * 68 + xp];
            float b10 = sb[yc * 68 + xm],                          b12 = sb[yc * 68 + xp];
            float b20 = sb[yp * 68 + xm], b21 = sb[yp * 68 + xc], b22 = sb[yp * 68 + xp];
            float gxv = (b02 - b00) + 2.f * (b12 - b10) + (b22 - b20);
            float gyv = (b20 - b00) + 2.f * (b21 - b01) + (b22 - b02);
            v = sqrtf(gxv * gxv + gyv * gyv + 1e-6f);

            if ((unsigned)(r - 1) < 32u && (unsigned)(c - 1) < 64u) {
                float ax = fabsf(gxv), ay = fabsf(gyv);
                int axis;
                if (ay < 0.41421356f * ax)      axis = 0;   // tan(22.5)
                else if (ay > 2.41421356f * ax) axis = 2;   // tan(67.5)
                else axis = (gxv * gyv >= 0.f) ? 1 : 3;
                sax[(r - 1) * 64 + (c - 1)] = (unsigned char)axis;
            }
        }
        sm[i] = v;
    }
    __syncthreads();

    // NMS + float4 store: each thread one float4 (4 adjacent x)
    for (int i = tid; i < 512; i += 512) {
        int y = i / 16, x4 = (i - 16 * y) * 4;
        float4 r4;
        float* rr = (float*)&r4;
        #pragma unroll
        for (int j = 0; j < 4; j++) {
            int x = x4 + j;
            int axis = sax[y * 64 + x];
            int dy = (axis == 0) ? 0 : 1;
            int dx = (axis == 2) ? 0 : ((axis == 3) ? -1 : 1);
            float m   = sm[(y + 1) * 66 + (x + 1)];
            float pos = m - sm[(y + 1 + dy) * 66 + (x + 1 + dx)];
            float neg = m - sm[(y + 1 - dy) * 66 + (x + 1 - dx)];
            rr[j] = (fminf(pos, neg) > 0.f) ? m : 0.f;
        }
        *(float4*)&outmag[(size_t)b * HW + (size_t)(ty0 + y) * W + tx0 + x4] = r4;
    }
}

// ---------------------------------------------------------------------------
// Kernel 3: 4 dilations (SAME max-pool, k=3,5,7,9) in one pass.
// 64x32 tile, 512 threads, float4 loads + float4 stores per output array.
// ---------------------------------------------------------------------------
__global__ __launch_bounds__(512) void k3_dilate(
    const float* __restrict__ mag,
    float* __restrict__ o3, float* __restrict__ o5,
    float* __restrict__ o7, float* __restrict__ o9)
{
    __shared__ float s [40 * 72];         // mag: rows -4..35, cols -4..67 (0 outside)
    __shared__ float v3[32 * 72];
    __shared__ float v5[32 * 72];
    __shared__ float v7[32 * 72];
    __shared__ float v9[32 * 72];

    const int tid = threadIdx.x;
    const int b = blockIdx.z;
    const int ty0 = blockIdx.y * TY;
    const int tx0 = blockIdx.x * TX;
    const float* m = mag + (size_t)b * HW;
    const bool xborder = (blockIdx.x == 0) | (blockIdx.x == (W/TX - 1));

    if (!xborder) {
        for (int i = tid; i < 40 * 18; i += 512) {
            int r = i / 18, c4 = i - 18 * r;
            int gy = ty0 + r - 4;
            float4 v = make_float4(0.f, 0.f, 0.f, 0.f);
            if (gy >= 0 && gy < H)
                v = *(const float4*)(m + gy * W + tx0 - 4 + c4 * 4);
            *(float4*)&s[r * 72 + c4 * 4] = v;
        }
    } else {
        for (int i = tid; i < 40 * 72; i += 512) {
            int r = i / 72, c = i - 72 * r;
            int gy = ty0 + r - 4, gx = tx0 + c - 4;
            s[i] = (gy >= 0 && gy < H && gx >= 0 && gx < W) ? m[gy * W + gx] : 0.f;
        }
    }
    __syncthreads();

    // vertical incremental maxes for output rows 0..31, all 72 cols
    for (int i = tid; i < 32 * 72; i += 512) {
        int r = i / 72, c = i - 72 * r;
        const float* p = &s[r * 72 + c];
        float t3 = fmaxf(fmaxf(p[3 * 72], p[4 * 72]), p[5 * 72]);
        float t5 = fmaxf(t3, fmaxf(p[2 * 72], p[6 * 72]));
        float t7 = fmaxf(t5, fmaxf(p[1 * 72], p[7 * 72]));
        float t9 = fmaxf(t7, fmaxf(p[0],      p[8 * 72]));
        v3[i] = t3; v5[i] = t5; v7[i] = t7; v9[i] = t9;
    }
    __syncthreads();

    // horizontal pass: each thread one float4 per output array
    for (int i = tid; i < 512; i += 512) {
        int y = i / 16, x4 = (i - 16 * y) * 4;
        float4 r3, r5, r7, r9;
        float *p3 = (float*)&r3, *p5 = (float*)&r5, *p7 = (float*)&r7, *p9 = (float*)&r9;
        #pragma unroll
        for (int j = 0; j < 4; j++) {
            int base = y * 72 + x4 + j;   // center col is x+4
            float a3 = fmaxf(fmaxf(v3[base + 3], v3[base + 4]), v3[base + 5]);
            float a5 = fmaxf(fmaxf(v5[base + 2], v5[base + 3]),
                       fmaxf(v5[base + 4], fmaxf(v5[base + 5], v5[base + 6])));
            float a7 = fmaxf(fmaxf(fmaxf(v7[base + 1], v7[base + 2]),
                                   fmaxf(v7[base + 3], v7[base + 4])),
                             fmaxf(fmaxf(v7[base + 5], v7[base + 6]), v7[base + 7]));
            float a9 = fmaxf(fmaxf(fmaxf(fmaxf(v9[base + 0], v9[base + 1]),
                                         fmaxf(v9[base + 2], v9[base + 3])),
                                   fmaxf(fmaxf(v9[base + 4], v9[base + 5]),
                                         fmaxf(v9[base + 6], v9[base + 7]))),
                             v9[base + 8]);
            p3[j] = a3; p5[j] = a5; p7[j] = a7; p9[j] = a9;
        }
        size_t o = (size_t)b * HW + (size_t)(ty0 + y) * W + tx0 + x4;
        *(float4*)&o3[o] = r3;
        *(float4*)&o5[o] = r5;
        *(float4*)&o7[o] = r7;
        *(float4*)&o9[o] = r9;
    }
}

// ---------------------------------------------------------------------------
extern "C" void kernel_launch(void* const* d_in, const int* in_sizes, int n_in,
                              void* d_out, int out_size)
{
    const float* x    = (const float*)d_in[0];
    const int*   perm = (const int*)d_in[1];
    float* out = (float*)d_out;

    float* o_mag = out;
    float* o_d3  = out + 1 * (size_t)B * HW;
    float* o_d5  = out + 2 * (size_t)B * HW;
    float* o_d7  = out + 3 * (size_t)B * HW;
    float* o_d9  = out + 4 * (size_t)B * HW;
    float* o_x5  = out + 5 * (size_t)B * HW;

    int nthreads1 = B * (HW / 8);   // 2 float4 chunks per thread
    k1_gray_shuffle<<<(nthreads1 + 255) / 256, 256>>>(x, perm, o_x5);

    dim3 g2(W / TX, H / TY, B);
    k2_canny<<<g2, 512>>>(o_mag);
    k3_dilate<<<g2, 512>>>(o_mag, o_d3, o_d5, o_d7, o_d9);
}